// round 4
// baseline (speedup 1.0000x reference)
#include <cuda_runtime.h>
#include <cuda_bf16.h>
#include <cstdint>

#define B_    128
#define LQ_   512
#define LD_   512
#define DIM   128
#define TM    128            // q rows per CTA
#define TN    128            // doc rows per chunk
#define NCHUNK (LD_ / TN)    // 4
#define NTHREADS 256

// ---- smem layout (bytes) ----
#define SM_QS    0                      // 128x128 bf16 swizzled = 32768
#define SM_DS0   32768                  // 32768
#define SM_DS1   65536                  // 32768
#define SM_DSQ0  98304                  // 512
#define SM_DSQ1  98816                  // 512
#define SM_QSQ   99328                  // 512
#define SM_MAX   99840                  // 128*4*4 = 2048
#define SM_RED   101888                 // 32
#define SMEM_TOTAL (SM_RED + 64)

__device__ __forceinline__ uint32_t smem_u32(const void* p) {
    uint32_t a;
    asm("{ .reg .u64 t; cvta.to.shared.u64 t, %1; cvt.u32.u64 %0, t; }" : "=r"(a) : "l"(p));
    return a;
}

__device__ __forceinline__ void ldmatrix_x4(uint32_t& r0, uint32_t& r1,
                                            uint32_t& r2, uint32_t& r3, uint32_t addr) {
    asm volatile("ldmatrix.sync.aligned.m8n8.x4.shared.b16 {%0,%1,%2,%3}, [%4];"
                 : "=r"(r0), "=r"(r1), "=r"(r2), "=r"(r3) : "r"(addr));
}

__device__ __forceinline__ void mma_16816(float& c0, float& c1, float& c2, float& c3,
                                          uint32_t a0, uint32_t a1, uint32_t a2, uint32_t a3,
                                          uint32_t b0, uint32_t b1) {
    asm volatile("mma.sync.aligned.m16n8k16.row.col.f32.bf16.bf16.f32 "
                 "{%0,%1,%2,%3}, {%4,%5,%6,%7}, {%8,%9}, {%0,%1,%2,%3};"
                 : "+f"(c0), "+f"(c1), "+f"(c2), "+f"(c3)
                 : "r"(a0), "r"(a1), "r"(a2), "r"(a3), "r"(b0), "r"(b1));
}

// convert one fp32 float4 row-piece to bf16 (optionally pre-scaled), store swizzled,
// and fold the full-row norm (of the UNSCALED values) via warp shuffles.
__device__ __forceinline__ void convert_store(float4 v, int row, int l,
                                              char* dst, float* nrm, float scale) {
    float s = v.x * v.x + v.y * v.y + v.z * v.z + v.w * v.w;
    #pragma unroll
    for (int o = 16; o > 0; o >>= 1) s += __shfl_xor_sync(0xffffffffu, s, o);
    if (l == 0) nrm[row] = s;
    __nv_bfloat162 p0 = __floats2bfloat162_rn(v.x * scale, v.y * scale);
    __nv_bfloat162 p1 = __floats2bfloat162_rn(v.z * scale, v.w * scale);
    uint2 pk = make_uint2(*reinterpret_cast<uint32_t*>(&p0),
                          *reinterpret_cast<uint32_t*>(&p1));
    uint32_t addr = (uint32_t)(row * 256 + (((l >> 1) ^ (row & 7)) << 4) + ((l & 1) << 3));
    *reinterpret_cast<uint2*>(dst + addr) = pk;
}

__global__ void zero_out_kernel(float* out) {
    if (threadIdx.x < B_) out[threadIdx.x] = 0.0f;
}

__global__ void __launch_bounds__(NTHREADS, 2)
colbert_mma_kernel(const float* __restrict__ Qg,
                   const float* __restrict__ Dg,
                   float* __restrict__ out) {
    extern __shared__ char smem[];
    const uint32_t sb = smem_u32(smem);
    float* qsq    = reinterpret_cast<float*>(smem + SM_QSQ);
    float* maxbuf = reinterpret_cast<float*>(smem + SM_MAX);
    float* red    = reinterpret_cast<float*>(smem + SM_RED);

    const int tid = threadIdx.x;
    const int w = tid >> 5, l = tid & 31;
    const int wm = w >> 2;               // 0..1 : 64-row M block
    const int wn = w & 3;                // 0..3 : 32-col N block

    const int b  = blockIdx.x >> 2;      // 4 q-tiles per batch
    const int qt = blockIdx.x & 3;
    const float* Qb = Qg + ((size_t)(b * LQ_ + qt * TM)) * DIM;
    const float* Db = Dg + (size_t)b * LD_ * DIM;

    // ---- convert Q tile fp32 -> bf16(2*q) swizzled smem, fused row norms ----
    {
        char* qs = smem + SM_QS;
        #pragma unroll
        for (int j = 0; j < TM / 8; j++) {
            int row = j * 8 + w;
            float4 v = reinterpret_cast<const float4*>(Qb)[row * 32 + l];
            convert_store(v, row, l, qs, qsq, 2.0f);   // 2*q exact in bf16
        }
    }
    // ---- convert chunk 0 into DS0 ----
    {
        char* ds_ = smem + SM_DS0;
        float* dsq0 = reinterpret_cast<float*>(smem + SM_DSQ0);
        #pragma unroll
        for (int j = 0; j < TN / 8; j++) {
            int row = j * 8 + w;
            float4 v = reinterpret_cast<const float4*>(Db)[row * 32 + l];
            convert_store(v, row, l, ds_, dsq0, 1.0f);
        }
    }

    // ---- ldmatrix lane addressing (as validated in round 3) ----
    const int jj = l >> 3;
    const int rr = l & 7;
    const int arow = wm * 64 + ((jj & 1) << 3) + rr;
    const int achunk_off = jj >> 1;
    const int asw = arow & 7;
    const int brow = wn * 32 + ((jj >> 1) << 3) + rr;
    const int bchunk_off = jj & 1;
    const int bsw = brow & 7;

    const int tg = l >> 2;
    const int tc = l & 3;

    float rlo[4], rhi[4];
    #pragma unroll
    for (int mt = 0; mt < 4; mt++) { rlo[mt] = -3.402823e38f; rhi[mt] = -3.402823e38f; }

    __syncthreads();

    for (int c = 0; c < NCHUNK; c++) {
        const int cur = c & 1;
        char* ds_cur = smem + SM_DS0 + cur * 32768;
        char* ds_nxt = smem + SM_DS0 + (cur ^ 1) * 32768;
        float* dsq_cur = reinterpret_cast<float*>(smem + SM_DSQ0 + cur * 512);
        float* dsq_nxt = reinterpret_cast<float*>(smem + SM_DSQ0 + (cur ^ 1) * 512);
        const uint32_t ds_cur_u = sb + SM_DS0 + (uint32_t)(cur * 32768);
        const bool pf = (c < NCHUNK - 1);
        const float4* nsrc = reinterpret_cast<const float4*>(Db + (size_t)((c + 1) * TN) * DIM);

        float acc[4][4][4];
        #pragma unroll
        for (int mt = 0; mt < 4; mt++)
            #pragma unroll
            for (int nt = 0; nt < 4; nt++)
                #pragma unroll
                for (int e = 0; e < 4; e++) acc[mt][nt][e] = 0.0f;

        // pipeline prologue: load pair 0 of next chunk
        float4 st0, st1;
        if (pf) {
            st0 = nsrc[(0 * 8 + w) * 32 + l];
            st1 = nsrc[(1 * 8 + w) * 32 + l];
        }

        #pragma unroll
        for (int k = 0; k < 8; k++) {
            // issue next pair's loads (used at step k+1)
            float4 n0, n1;
            if (pf && k < 7) {
                n0 = nsrc[((2 * (k + 1)) * 8 + w) * 32 + l];
                n1 = nsrc[((2 * (k + 1) + 1) * 8 + w) * 32 + l];
            }

            uint32_t a[4][4];
            #pragma unroll
            for (int mt = 0; mt < 4; mt++) {
                uint32_t addr = sb + SM_QS + (uint32_t)((arow + mt * 16) * 256
                              + (((k * 2 + achunk_off) ^ asw) << 4));
                ldmatrix_x4(a[mt][0], a[mt][1], a[mt][2], a[mt][3], addr);
            }
            uint32_t bf[4][2];
            #pragma unroll
            for (int p = 0; p < 2; p++) {
                uint32_t addr = ds_cur_u + (uint32_t)((brow + p * 16) * 256
                              + (((k * 2 + bchunk_off) ^ bsw) << 4));
                uint32_t r0, r1, r2, r3;
                ldmatrix_x4(r0, r1, r2, r3, addr);
                bf[p * 2 + 0][0] = r0; bf[p * 2 + 0][1] = r1;
                bf[p * 2 + 1][0] = r2; bf[p * 2 + 1][1] = r3;
            }
            #pragma unroll
            for (int mt = 0; mt < 4; mt++)
                #pragma unroll
                for (int nt = 0; nt < 4; nt++)
                    mma_16816(acc[mt][nt][0], acc[mt][nt][1], acc[mt][nt][2], acc[mt][nt][3],
                              a[mt][0], a[mt][1], a[mt][2], a[mt][3],
                              bf[nt][0], bf[nt][1]);

            // convert the pair loaded last step into the inactive buffer
            if (pf) {
                convert_store(st0, 16 * k + w,     l, ds_nxt, dsq_nxt, 1.0f);
                convert_store(st1, 16 * k + 8 + w, l, ds_nxt, dsq_nxt, 1.0f);
                st0 = n0; st1 = n1;
            }
        }

        // ---- fused epilogue: neg_dist = (2q).d - d^2 ; running max ----
        #pragma unroll
        for (int nt = 0; nt < 4; nt++) {
            float2 ds2 = *reinterpret_cast<float2*>(&dsq_cur[wn * 32 + nt * 8 + tc * 2]);
            #pragma unroll
            for (int mt = 0; mt < 4; mt++) {
                float s0 = acc[mt][nt][0] - ds2.x;
                float s1 = acc[mt][nt][1] - ds2.y;
                float s2 = acc[mt][nt][2] - ds2.x;
                float s3 = acc[mt][nt][3] - ds2.y;
                rlo[mt] = fmaxf(rlo[mt], fmaxf(s0, s1));
                rhi[mt] = fmaxf(rhi[mt], fmaxf(s2, s3));
            }
        }
        __syncthreads();   // next buffer fully written; cur buffer free for c+2 writes
    }

    // ---- cross-lane max (cols live in lane bits 0..1) ----
    #pragma unroll
    for (int mt = 0; mt < 4; mt++) {
        rlo[mt] = fmaxf(rlo[mt], __shfl_xor_sync(0xffffffffu, rlo[mt], 1));
        rlo[mt] = fmaxf(rlo[mt], __shfl_xor_sync(0xffffffffu, rlo[mt], 2));
        rhi[mt] = fmaxf(rhi[mt], __shfl_xor_sync(0xffffffffu, rhi[mt], 1));
        rhi[mt] = fmaxf(rhi[mt], __shfl_xor_sync(0xffffffffu, rhi[mt], 2));
    }
    if (tc == 0) {
        #pragma unroll
        for (int mt = 0; mt < 4; mt++) {
            maxbuf[(wm * 64 + mt * 16 + tg) * 4 + wn]     = rlo[mt];
            maxbuf[(wm * 64 + mt * 16 + 8 + tg) * 4 + wn] = rhi[mt];
        }
    }
    __syncthreads();

    // ---- final: row max across 4 warp-cols, subtract ||q||^2, block sum ----
    float val = 0.0f;
    if (tid < TM) {
        float4 m4 = *reinterpret_cast<float4*>(&maxbuf[tid * 4]);
        val = fmaxf(fmaxf(m4.x, m4.y), fmaxf(m4.z, m4.w)) - qsq[tid];
    }
    #pragma unroll
    for (int o = 16; o > 0; o >>= 1) val += __shfl_xor_sync(0xffffffffu, val, o);
    if (l == 0) red[w] = val;
    __syncthreads();
    if (tid == 0) {
        float s = 0.0f;
        #pragma unroll
        for (int i = 0; i < 8; i++) s += red[i];
        atomicAdd(&out[b], s);
    }
}

extern "C" void kernel_launch(void* const* d_in, const int* in_sizes, int n_in,
                              void* d_out, int out_size) {
    const float* Qg = (const float*)d_in[0];
    const float* Dg = (const float*)d_in[1];
    float* out = (float*)d_out;

    static int attr_set = 0;
    if (!attr_set) {
        cudaFuncSetAttribute(colbert_mma_kernel,
                             cudaFuncAttributeMaxDynamicSharedMemorySize, SMEM_TOTAL);
        attr_set = 1;
    }

    zero_out_kernel<<<1, 128>>>(out);
    colbert_mma_kernel<<<B_ * (LQ_ / TM), NTHREADS, SMEM_TOTAL>>>(Qg, Dg, out);
}

// round 5
// speedup vs baseline: 1.1454x; 1.1454x over previous
#include <cuda_runtime.h>
#include <cuda_bf16.h>
#include <cstdint>

#define B_    128
#define LQ_   512
#define LD_   512
#define DIM   128
#define TM    128            // q rows per CTA
#define TN    128            // doc rows per chunk
#define NCHUNK (LD_ / TN)    // 4
#define NTHREADS 256

// ---- global scratch: pre-converted bf16 D + exact fp32 row norms ----
__device__ __nv_bfloat16 g_Dbf[B_ * LD_ * DIM];   // 16 MB
__device__ float         g_Dsq[B_ * LD_];         // 256 KB

// ---- kernel-2 smem layout (bytes) ----
#define SM_QS    0                      // 128x128 bf16 swizzled = 32768
#define SM_DS0   32768                  // bf16 chunk buf 0 (32768)
#define SM_DS1   65536                  // bf16 chunk buf 1 (32768)
#define SM_DSQ   98304                  // 512 floats (whole batch) = 2048
#define SM_QSQ   100352                 // 128 floats = 512
#define SM_MAX   100864                 // 128*4 floats = 2048
#define SM_RED   102912                 // 8 floats
#define SMEM_TOTAL (SM_RED + 64)

__device__ __forceinline__ uint32_t smem_u32(const void* p) {
    uint32_t a;
    asm("{ .reg .u64 t; cvta.to.shared.u64 t, %1; cvt.u32.u64 %0, t; }" : "=r"(a) : "l"(p));
    return a;
}

__device__ __forceinline__ void ldmatrix_x4(uint32_t& r0, uint32_t& r1,
                                            uint32_t& r2, uint32_t& r3, uint32_t addr) {
    asm volatile("ldmatrix.sync.aligned.m8n8.x4.shared.b16 {%0,%1,%2,%3}, [%4];"
                 : "=r"(r0), "=r"(r1), "=r"(r2), "=r"(r3) : "r"(addr));
}

__device__ __forceinline__ void mma_16816(float& c0, float& c1, float& c2, float& c3,
                                          uint32_t a0, uint32_t a1, uint32_t a2, uint32_t a3,
                                          uint32_t b0, uint32_t b1) {
    asm volatile("mma.sync.aligned.m16n8k16.row.col.f32.bf16.bf16.f32 "
                 "{%0,%1,%2,%3}, {%4,%5,%6,%7}, {%8,%9}, {%0,%1,%2,%3};"
                 : "+f"(c0), "+f"(c1), "+f"(c2), "+f"(c3)
                 : "r"(a0), "r"(a1), "r"(a2), "r"(a3), "r"(b0), "r"(b1));
}

__device__ __forceinline__ void cp_async16(uint32_t dst, const void* src) {
    asm volatile("cp.async.cg.shared.global [%0], [%1], 16;" :: "r"(dst), "l"(src));
}
__device__ __forceinline__ void cp_commit() {
    asm volatile("cp.async.commit_group;" ::: "memory");
}
template <int N>
__device__ __forceinline__ void cp_wait() {
    asm volatile("cp.async.wait_group %0;" :: "n"(N) : "memory");
}

__global__ void zero_out_kernel(float* out) {
    if (threadIdx.x < B_) out[threadIdx.x] = 0.0f;
}

// ================= kernel 1: D fp32 -> bf16 + exact row norms =================
// grid 512 x 256. CTA handles 128 rows. Warp: 4 rows/pass, 8 lanes/row.
__global__ void __launch_bounds__(NTHREADS)
convert_d_kernel(const float* __restrict__ Dg) {
    const int tid = threadIdx.x;
    const int w = tid >> 5, l = tid & 31;
    const int rsub = l >> 3;            // row within group of 4
    const int piece = l & 7;            // float4 piece

    #pragma unroll
    for (int pass = 0; pass < 4; pass++) {
        int row = blockIdx.x * 128 + w * 16 + pass * 4 + rsub;
        const float4* src = reinterpret_cast<const float4*>(Dg + (size_t)row * DIM);
        float4 v[4];
        #pragma unroll
        for (int i = 0; i < 4; i++) v[i] = src[piece + 8 * i];

        float s = 0.0f;
        #pragma unroll
        for (int i = 0; i < 4; i++)
            s += v[i].x * v[i].x + v[i].y * v[i].y + v[i].z * v[i].z + v[i].w * v[i].w;
        s += __shfl_xor_sync(0xffffffffu, s, 1);
        s += __shfl_xor_sync(0xffffffffu, s, 2);
        s += __shfl_xor_sync(0xffffffffu, s, 4);
        if (piece == 0) g_Dsq[row] = s;

        uint2* drow = reinterpret_cast<uint2*>(g_Dbf + (size_t)row * DIM);
        #pragma unroll
        for (int i = 0; i < 4; i++) {
            __nv_bfloat162 p0 = __floats2bfloat162_rn(v[i].x, v[i].y);
            __nv_bfloat162 p1 = __floats2bfloat162_rn(v[i].z, v[i].w);
            drow[piece + 8 * i] = make_uint2(*reinterpret_cast<uint32_t*>(&p0),
                                             *reinterpret_cast<uint32_t*>(&p1));
        }
    }
}

// ================= kernel 2: GEMM + fused max/sum epilogue =================
__global__ void __launch_bounds__(NTHREADS, 2)
colbert_mma_kernel(const float* __restrict__ Qg, float* __restrict__ out) {
    extern __shared__ char smem[];
    const uint32_t sb = smem_u32(smem);
    float* dsq_s  = reinterpret_cast<float*>(smem + SM_DSQ);
    float* qsq    = reinterpret_cast<float*>(smem + SM_QSQ);
    float* maxbuf = reinterpret_cast<float*>(smem + SM_MAX);
    float* red    = reinterpret_cast<float*>(smem + SM_RED);

    const int tid = threadIdx.x;
    const int w = tid >> 5, l = tid & 31;
    const int wm = w >> 2;               // 0..1
    const int wn = w & 3;                // 0..3

    const int b  = blockIdx.x >> 2;
    const int qt = blockIdx.x & 3;
    const float* Qb = Qg + ((size_t)(b * LQ_ + qt * TM)) * DIM;
    const __nv_bfloat16* Dbf_b = g_Dbf + (size_t)b * LD_ * DIM;

    // ---- issue cp.async for chunks 0 and 1 (bf16, swizzled dst) ----
    // 2048 16B-granules per chunk; thread covers idx = tid + 256*j.
    {
        #pragma unroll
        for (int cbuf = 0; cbuf < 2; cbuf++) {
            const char* src_base = reinterpret_cast<const char*>(Dbf_b + (size_t)cbuf * TN * DIM);
            uint32_t dst_base = sb + SM_DS0 + (uint32_t)(cbuf * 32768);
            #pragma unroll
            for (int j = 0; j < 8; j++) {
                int idx = tid + 256 * j;
                int r = idx >> 4, cc = idx & 15;
                cp_async16(dst_base + (uint32_t)(r * 256 + (((cc ^ (r & 7)) << 4))),
                           src_base + r * 256 + cc * 16);
            }
            cp_commit();
        }
    }

    // ---- convert Q tile fp32 -> bf16(2*q) swizzled smem + qsq (overlapped) ----
    {
        char* qs = smem + SM_QS;
        #pragma unroll
        for (int j = 0; j < TM / 8; j++) {
            int row = j * 8 + w;
            float4 v = reinterpret_cast<const float4*>(Qb)[row * 32 + l];
            float s = v.x * v.x + v.y * v.y + v.z * v.z + v.w * v.w;
            #pragma unroll
            for (int o = 16; o > 0; o >>= 1) s += __shfl_xor_sync(0xffffffffu, s, o);
            if (l == 0) qsq[row] = s;
            __nv_bfloat162 p0 = __floats2bfloat162_rn(2.0f * v.x, 2.0f * v.y);
            __nv_bfloat162 p1 = __floats2bfloat162_rn(2.0f * v.z, 2.0f * v.w);
            uint2 pk = make_uint2(*reinterpret_cast<uint32_t*>(&p0),
                                  *reinterpret_cast<uint32_t*>(&p1));
            uint32_t addr = (uint32_t)(row * 256 + (((l >> 1) ^ (row & 7)) << 4) + ((l & 1) << 3));
            *reinterpret_cast<uint2*>(qs + addr) = pk;
        }
    }
    // ---- whole-batch doc norms into smem (512 floats) ----
    {
        const float* src = g_Dsq + b * LD_;
        dsq_s[tid] = src[tid];
        dsq_s[tid + 256] = src[tid + 256];
    }

    // ---- ldmatrix lane addressing (validated round 3) ----
    const int jj = l >> 3;
    const int rr = l & 7;
    const int arow = wm * 64 + ((jj & 1) << 3) + rr;
    const int achunk_off = jj >> 1;
    const int asw = arow & 7;
    const int brow = wn * 32 + ((jj >> 1) << 3) + rr;
    const int bchunk_off = jj & 1;
    const int bsw = brow & 7;

    const int tg = l >> 2;
    const int tc = l & 3;

    float rlo[4], rhi[4];
    #pragma unroll
    for (int mt = 0; mt < 4; mt++) { rlo[mt] = -3.402823e38f; rhi[mt] = -3.402823e38f; }

    #pragma unroll
    for (int c = 0; c < NCHUNK; c++) {
        if (c < NCHUNK - 1) cp_wait<1>(); else cp_wait<0>();
        __syncthreads();   // chunk c visible to all; also protects buffer reuse

        const uint32_t ds_cur_u = sb + SM_DS0 + (uint32_t)((c & 1) * 32768);

        float acc[4][4][4];
        #pragma unroll
        for (int mt = 0; mt < 4; mt++)
            #pragma unroll
            for (int nt = 0; nt < 4; nt++)
                #pragma unroll
                for (int e = 0; e < 4; e++) acc[mt][nt][e] = 0.0f;

        #pragma unroll
        for (int k = 0; k < 8; k++) {
            uint32_t a[4][4];
            #pragma unroll
            for (int mt = 0; mt < 4; mt++) {
                uint32_t addr = sb + SM_QS + (uint32_t)((arow + mt * 16) * 256
                              + (((k * 2 + achunk_off) ^ asw) << 4));
                ldmatrix_x4(a[mt][0], a[mt][1], a[mt][2], a[mt][3], addr);
            }
            uint32_t bf[4][2];
            #pragma unroll
            for (int p = 0; p < 2; p++) {
                uint32_t addr = ds_cur_u + (uint32_t)((brow + p * 16) * 256
                              + (((k * 2 + bchunk_off) ^ bsw) << 4));
                uint32_t r0, r1, r2, r3;
                ldmatrix_x4(r0, r1, r2, r3, addr);
                bf[p * 2 + 0][0] = r0; bf[p * 2 + 0][1] = r1;
                bf[p * 2 + 1][0] = r2; bf[p * 2 + 1][1] = r3;
            }
            #pragma unroll
            for (int mt = 0; mt < 4; mt++)
                #pragma unroll
                for (int nt = 0; nt < 4; nt++)
                    mma_16816(acc[mt][nt][0], acc[mt][nt][1], acc[mt][nt][2], acc[mt][nt][3],
                              a[mt][0], a[mt][1], a[mt][2], a[mt][3],
                              bf[nt][0], bf[nt][1]);
        }

        // ---- fused epilogue: neg_dist = (2q).d - d^2 ; running max ----
        #pragma unroll
        for (int nt = 0; nt < 4; nt++) {
            float2 ds2 = *reinterpret_cast<float2*>(&dsq_s[c * TN + wn * 32 + nt * 8 + tc * 2]);
            #pragma unroll
            for (int mt = 0; mt < 4; mt++) {
                rlo[mt] = fmaxf(rlo[mt], fmaxf(acc[mt][nt][0] - ds2.x, acc[mt][nt][1] - ds2.y));
                rhi[mt] = fmaxf(rhi[mt], fmaxf(acc[mt][nt][2] - ds2.x, acc[mt][nt][3] - ds2.y));
            }
        }

        // ---- refill this buffer with chunk c+2 ----
        if (c < NCHUNK - 2) {
            __syncthreads();   // all warps done reading buf (ldmatrix) before overwrite
            const char* src_base = reinterpret_cast<const char*>(Dbf_b + (size_t)(c + 2) * TN * DIM);
            uint32_t dst_base = sb + SM_DS0 + (uint32_t)((c & 1) * 32768);
            #pragma unroll
            for (int j = 0; j < 8; j++) {
                int idx = tid + 256 * j;
                int r = idx >> 4, cc = idx & 15;
                cp_async16(dst_base + (uint32_t)(r * 256 + (((cc ^ (r & 7)) << 4))),
                           src_base + r * 256 + cc * 16);
            }
            cp_commit();
        }
    }

    // ---- cross-lane max (cols in lane bits 0..1) ----
    #pragma unroll
    for (int mt = 0; mt < 4; mt++) {
        rlo[mt] = fmaxf(rlo[mt], __shfl_xor_sync(0xffffffffu, rlo[mt], 1));
        rlo[mt] = fmaxf(rlo[mt], __shfl_xor_sync(0xffffffffu, rlo[mt], 2));
        rhi[mt] = fmaxf(rhi[mt], __shfl_xor_sync(0xffffffffu, rhi[mt], 1));
        rhi[mt] = fmaxf(rhi[mt], __shfl_xor_sync(0xffffffffu, rhi[mt], 2));
    }
    if (tc == 0) {
        #pragma unroll
        for (int mt = 0; mt < 4; mt++) {
            maxbuf[(wm * 64 + mt * 16 + tg) * 4 + wn]     = rlo[mt];
            maxbuf[(wm * 64 + mt * 16 + 8 + tg) * 4 + wn] = rhi[mt];
        }
    }
    __syncthreads();

    // ---- row max across 4 warp-cols, subtract ||q||^2, block sum ----
    float val = 0.0f;
    if (tid < TM) {
        float4 m4 = *reinterpret_cast<float4*>(&maxbuf[tid * 4]);
        val = fmaxf(fmaxf(m4.x, m4.y), fmaxf(m4.z, m4.w)) - qsq[tid];
    }
    #pragma unroll
    for (int o = 16; o > 0; o >>= 1) val += __shfl_xor_sync(0xffffffffu, val, o);
    if (l == 0) red[w] = val;
    __syncthreads();
    if (tid == 0) {
        float s = 0.0f;
        #pragma unroll
        for (int i = 0; i < 8; i++) s += red[i];
        atomicAdd(&out[b], s);
    }
}

extern "C" void kernel_launch(void* const* d_in, const int* in_sizes, int n_in,
                              void* d_out, int out_size) {
    const float* Qg = (const float*)d_in[0];
    const float* Dg = (const float*)d_in[1];
    float* out = (float*)d_out;

    static int attr_set = 0;
    if (!attr_set) {
        cudaFuncSetAttribute(colbert_mma_kernel,
                             cudaFuncAttributeMaxDynamicSharedMemorySize, SMEM_TOTAL);
        attr_set = 1;
    }

    zero_out_kernel<<<1, 128>>>(out);
    convert_d_kernel<<<(B_ * LD_) / 128, NTHREADS>>>(Dg);
    colbert_mma_kernel<<<B_ * (LQ_ / TM), NTHREADS, SMEM_TOTAL>>>(Qg, out);
}

// round 6
// speedup vs baseline: 1.1869x; 1.0363x over previous
#include <cuda_runtime.h>
#include <cuda_bf16.h>
#include <cstdint>

#define B_    128
#define LQ_   512
#define LD_   512
#define DIM   128
#define TM    128            // q rows per CTA
#define TN    128            // doc rows per chunk
#define NCHUNK (LD_ / TN)    // 4
#define NTHREADS 256

// ---- global scratch: pre-converted bf16 D + exact fp32 row norms ----
__device__ __nv_bfloat16 g_Dbf[B_ * LD_ * DIM];   // 16 MB
__device__ float         g_Dsq[B_ * LD_];         // 256 KB

// ---- kernel-2 smem layout (bytes) ----
#define SM_QS    0                      // 128x128 bf16 swizzled = 32768
#define SM_DS0   32768                  // bf16 chunk buf 0 (32768)
#define SM_DS1   65536                  // bf16 chunk buf 1 (32768)
#define SM_DSQ   98304                  // 512 floats (whole batch) = 2048
#define SM_QSQ   100352                 // 128 floats = 512
#define SM_MAX   100864                 // 128*4 floats = 2048
#define SM_RED   102912                 // 8 floats
#define SMEM_TOTAL (SM_RED + 64)

__device__ __forceinline__ uint32_t smem_u32(const void* p) {
    uint32_t a;
    asm("{ .reg .u64 t; cvta.to.shared.u64 t, %1; cvt.u32.u64 %0, t; }" : "=r"(a) : "l"(p));
    return a;
}

__device__ __forceinline__ void ldmatrix_x4(uint32_t& r0, uint32_t& r1,
                                            uint32_t& r2, uint32_t& r3, uint32_t addr) {
    asm volatile("ldmatrix.sync.aligned.m8n8.x4.shared.b16 {%0,%1,%2,%3}, [%4];"
                 : "=r"(r0), "=r"(r1), "=r"(r2), "=r"(r3) : "r"(addr));
}

__device__ __forceinline__ void mma_16816(float& c0, float& c1, float& c2, float& c3,
                                          uint32_t a0, uint32_t a1, uint32_t a2, uint32_t a3,
                                          uint32_t b0, uint32_t b1) {
    asm volatile("mma.sync.aligned.m16n8k16.row.col.f32.bf16.bf16.f32 "
                 "{%0,%1,%2,%3}, {%4,%5,%6,%7}, {%8,%9}, {%0,%1,%2,%3};"
                 : "+f"(c0), "+f"(c1), "+f"(c2), "+f"(c3)
                 : "r"(a0), "r"(a1), "r"(a2), "r"(a3), "r"(b0), "r"(b1));
}

__device__ __forceinline__ void cp_async16(uint32_t dst, const void* src) {
    asm volatile("cp.async.cg.shared.global [%0], [%1], 16;" :: "r"(dst), "l"(src));
}
__device__ __forceinline__ void cp_commit() {
    asm volatile("cp.async.commit_group;" ::: "memory");
}
template <int N>
__device__ __forceinline__ void cp_wait() {
    asm volatile("cp.async.wait_group %0;" :: "n"(N) : "memory");
}

// ================= kernel 1: D fp32 -> bf16 + exact row norms (+ zero out) ====
// grid 512 x 256. CTA handles 128 rows. Warp: 4 rows/pass, 8 lanes/row.
__global__ void __launch_bounds__(NTHREADS)
convert_d_kernel(const float* __restrict__ Dg, float* __restrict__ out) {
    const int tid = threadIdx.x;
    const int w = tid >> 5, l = tid & 31;
    const int rsub = l >> 3;            // row within group of 4
    const int piece = l & 7;            // float4 piece

    if (blockIdx.x == 0 && tid < B_) out[tid] = 0.0f;   // fused output zeroing

    #pragma unroll
    for (int pass = 0; pass < 4; pass++) {
        int row = blockIdx.x * 128 + w * 16 + pass * 4 + rsub;
        const float4* src = reinterpret_cast<const float4*>(Dg + (size_t)row * DIM);
        float4 v[4];
        #pragma unroll
        for (int i = 0; i < 4; i++) v[i] = src[piece + 8 * i];

        float s = 0.0f;
        #pragma unroll
        for (int i = 0; i < 4; i++)
            s += v[i].x * v[i].x + v[i].y * v[i].y + v[i].z * v[i].z + v[i].w * v[i].w;
        s += __shfl_xor_sync(0xffffffffu, s, 1);
        s += __shfl_xor_sync(0xffffffffu, s, 2);
        s += __shfl_xor_sync(0xffffffffu, s, 4);
        if (piece == 0) g_Dsq[row] = s;

        uint2* drow = reinterpret_cast<uint2*>(g_Dbf + (size_t)row * DIM);
        #pragma unroll
        for (int i = 0; i < 4; i++) {
            __nv_bfloat162 p0 = __floats2bfloat162_rn(v[i].x, v[i].y);
            __nv_bfloat162 p1 = __floats2bfloat162_rn(v[i].z, v[i].w);
            drow[piece + 8 * i] = make_uint2(*reinterpret_cast<uint32_t*>(&p0),
                                             *reinterpret_cast<uint32_t*>(&p1));
        }
    }
}

// ================= kernel 2: GEMM + fused max/sum epilogue =================
__global__ void __launch_bounds__(NTHREADS, 2)
colbert_mma_kernel(const float* __restrict__ Qg, float* __restrict__ out) {
    extern __shared__ char smem[];
    const uint32_t sb = smem_u32(smem);
    float* dsq_s  = reinterpret_cast<float*>(smem + SM_DSQ);
    float* qsq    = reinterpret_cast<float*>(smem + SM_QSQ);
    float* maxbuf = reinterpret_cast<float*>(smem + SM_MAX);
    float* red    = reinterpret_cast<float*>(smem + SM_RED);

    const int tid = threadIdx.x;
    const int w = tid >> 5, l = tid & 31;
    const int wm = w >> 2;               // 0..1
    const int wn = w & 3;                // 0..3

    const int b  = blockIdx.x >> 2;
    const int qt = blockIdx.x & 3;
    const float* Qb = Qg + ((size_t)(b * LQ_ + qt * TM)) * DIM;
    const __nv_bfloat16* Dbf_b = g_Dbf + (size_t)b * LD_ * DIM;

    // ---- issue cp.async for chunks 0 and 1 (bf16, swizzled dst) ----
    {
        #pragma unroll
        for (int cbuf = 0; cbuf < 2; cbuf++) {
            const char* src_base = reinterpret_cast<const char*>(Dbf_b + (size_t)cbuf * TN * DIM);
            uint32_t dst_base = sb + SM_DS0 + (uint32_t)(cbuf * 32768);
            #pragma unroll
            for (int j = 0; j < 8; j++) {
                int idx = tid + 256 * j;
                int r = idx >> 4, cc = idx & 15;
                cp_async16(dst_base + (uint32_t)(r * 256 + (((cc ^ (r & 7)) << 4))),
                           src_base + r * 256 + cc * 16);
            }
            cp_commit();
        }
    }

    // ---- convert Q tile fp32 -> bf16(2*q) swizzled smem + qsq (overlapped) ----
    {
        char* qs = smem + SM_QS;
        #pragma unroll
        for (int j = 0; j < TM / 8; j++) {
            int row = j * 8 + w;
            float4 v = reinterpret_cast<const float4*>(Qb)[row * 32 + l];
            float s = v.x * v.x + v.y * v.y + v.z * v.z + v.w * v.w;
            #pragma unroll
            for (int o = 16; o > 0; o >>= 1) s += __shfl_xor_sync(0xffffffffu, s, o);
            if (l == 0) qsq[row] = s;
            __nv_bfloat162 p0 = __floats2bfloat162_rn(2.0f * v.x, 2.0f * v.y);
            __nv_bfloat162 p1 = __floats2bfloat162_rn(2.0f * v.z, 2.0f * v.w);
            uint2 pk = make_uint2(*reinterpret_cast<uint32_t*>(&p0),
                                  *reinterpret_cast<uint32_t*>(&p1));
            uint32_t addr = (uint32_t)(row * 256 + (((l >> 1) ^ (row & 7)) << 4) + ((l & 1) << 3));
            *reinterpret_cast<uint2*>(qs + addr) = pk;
        }
    }
    // ---- whole-batch doc norms into smem (512 floats) ----
    {
        const float* src = g_Dsq + b * LD_;
        dsq_s[tid] = src[tid];
        dsq_s[tid + 256] = src[tid + 256];
    }

    // ---- ldmatrix lane addressing (validated round 3) ----
    const int jj = l >> 3;
    const int rr = l & 7;
    const int arow = wm * 64 + ((jj & 1) << 3) + rr;
    const int achunk_off = jj >> 1;
    const int asw = arow & 7;
    const int brow = wn * 32 + ((jj >> 1) << 3) + rr;
    const int bchunk_off = jj & 1;
    const int bsw = brow & 7;

    const int tg = l >> 2;
    const int tc = l & 3;

    float rlo[4], rhi[4];
    #pragma unroll
    for (int mt = 0; mt < 4; mt++) { rlo[mt] = -3.402823e38f; rhi[mt] = -3.402823e38f; }

    #pragma unroll
    for (int c = 0; c < NCHUNK; c++) {
        if (c < NCHUNK - 1) cp_wait<1>(); else cp_wait<0>();
        __syncthreads();   // chunk c visible to all

        const uint32_t ds_cur_u = sb + SM_DS0 + (uint32_t)((c & 1) * 32768);

        float acc[4][4][4];
        #pragma unroll
        for (int mt = 0; mt < 4; mt++)
            #pragma unroll
            for (int nt = 0; nt < 4; nt++)
                #pragma unroll
                for (int e = 0; e < 4; e++) acc[mt][nt][e] = 0.0f;

        #pragma unroll
        for (int k = 0; k < 8; k++) {
            uint32_t a[4][4];
            #pragma unroll
            for (int mt = 0; mt < 4; mt++) {
                uint32_t addr = sb + SM_QS + (uint32_t)((arow + mt * 16) * 256
                              + (((k * 2 + achunk_off) ^ asw) << 4));
                ldmatrix_x4(a[mt][0], a[mt][1], a[mt][2], a[mt][3], addr);
            }
            uint32_t bf[4][2];
            #pragma unroll
            for (int p = 0; p < 2; p++) {
                uint32_t addr = ds_cur_u + (uint32_t)((brow + p * 16) * 256
                              + (((k * 2 + bchunk_off) ^ bsw) << 4));
                uint32_t r0, r1, r2, r3;
                ldmatrix_x4(r0, r1, r2, r3, addr);
                bf[p * 2 + 0][0] = r0; bf[p * 2 + 0][1] = r1;
                bf[p * 2 + 1][0] = r2; bf[p * 2 + 1][1] = r3;
            }
            #pragma unroll
            for (int mt = 0; mt < 4; mt++)
                #pragma unroll
                for (int nt = 0; nt < 4; nt++)
                    mma_16816(acc[mt][nt][0], acc[mt][nt][1], acc[mt][nt][2], acc[mt][nt][3],
                              a[mt][0], a[mt][1], a[mt][2], a[mt][3],
                              bf[nt][0], bf[nt][1]);
        }

        // ---- refill this buffer with chunk c+2 ASAP (overlaps epilogue) ----
        if (c < NCHUNK - 2) {
            __syncthreads();   // all warps done with ldmatrix on this buffer
            const char* src_base = reinterpret_cast<const char*>(Dbf_b + (size_t)(c + 2) * TN * DIM);
            uint32_t dst_base = sb + SM_DS0 + (uint32_t)((c & 1) * 32768);
            #pragma unroll
            for (int j = 0; j < 8; j++) {
                int idx = tid + 256 * j;
                int r = idx >> 4, cc = idx & 15;
                cp_async16(dst_base + (uint32_t)(r * 256 + (((cc ^ (r & 7)) << 4))),
                           src_base + r * 256 + cc * 16);
            }
            cp_commit();
        }

        // ---- fused epilogue: neg_dist = (2q).d - d^2 ; running max ----
        #pragma unroll
        for (int nt = 0; nt < 4; nt++) {
            float2 ds2 = *reinterpret_cast<float2*>(&dsq_s[c * TN + wn * 32 + nt * 8 + tc * 2]);
            #pragma unroll
            for (int mt = 0; mt < 4; mt++) {
                rlo[mt] = fmaxf(rlo[mt], fmaxf(acc[mt][nt][0] - ds2.x, acc[mt][nt][1] - ds2.y));
                rhi[mt] = fmaxf(rhi[mt], fmaxf(acc[mt][nt][2] - ds2.x, acc[mt][nt][3] - ds2.y));
            }
        }
    }

    // ---- cross-lane max (cols in lane bits 0..1) ----
    #pragma unroll
    for (int mt = 0; mt < 4; mt++) {
        rlo[mt] = fmaxf(rlo[mt], __shfl_xor_sync(0xffffffffu, rlo[mt], 1));
        rlo[mt] = fmaxf(rlo[mt], __shfl_xor_sync(0xffffffffu, rlo[mt], 2));
        rhi[mt] = fmaxf(rhi[mt], __shfl_xor_sync(0xffffffffu, rhi[mt], 1));
        rhi[mt] = fmaxf(rhi[mt], __shfl_xor_sync(0xffffffffu, rhi[mt], 2));
    }
    if (tc == 0) {
        #pragma unroll
        for (int mt = 0; mt < 4; mt++) {
            maxbuf[(wm * 64 + mt * 16 + tg) * 4 + wn]     = rlo[mt];
            maxbuf[(wm * 64 + mt * 16 + 8 + tg) * 4 + wn] = rhi[mt];
        }
    }
    __syncthreads();

    // ---- row max across 4 warp-cols, subtract ||q||^2, block sum ----
    float val = 0.0f;
    if (tid < TM) {
        float4 m4 = *reinterpret_cast<float4*>(&maxbuf[tid * 4]);
        val = fmaxf(fmaxf(m4.x, m4.y), fmaxf(m4.z, m4.w)) - qsq[tid];
    }
    #pragma unroll
    for (int o = 16; o > 0; o >>= 1) val += __shfl_xor_sync(0xffffffffu, val, o);
    if (l == 0) red[w] = val;
    __syncthreads();
    if (tid == 0) {
        float s = 0.0f;
        #pragma unroll
        for (int i = 0; i < 8; i++) s += red[i];
        atomicAdd(&out[b], s);
    }
}

extern "C" void kernel_launch(void* const* d_in, const int* in_sizes, int n_in,
                              void* d_out, int out_size) {
    const float* Qg = (const float*)d_in[0];
    const float* Dg = (const float*)d_in[1];
    float* out = (float*)d_out;

    static int attr_set = 0;
    if (!attr_set) {
        cudaFuncSetAttribute(colbert_mma_kernel,
                             cudaFuncAttributeMaxDynamicSharedMemorySize, SMEM_TOTAL);
        attr_set = 1;
    }

    convert_d_kernel<<<(B_ * LD_) / 128, NTHREADS>>>(Dg, out);
    colbert_mma_kernel<<<B_ * (LQ_ / TM), NTHREADS, SMEM_TOTAL>>>(Qg, out);
}

// round 7
// speedup vs baseline: 1.2015x; 1.0122x over previous
#include <cuda_runtime.h>
#include <cuda_bf16.h>
#include <cstdint>

#define B_    128
#define LQ_   512
#define LD_   512
#define DIM   128
#define TM    128            // q rows per CTA
#define TN    128            // doc rows per chunk
#define NCHUNK (LD_ / TN)    // 4
#define NTHREADS 256

// ---- global scratch: pre-converted bf16 D + exact fp32 row norms ----
__device__ __nv_bfloat16 g_Dbf[B_ * LD_ * DIM];   // 16 MB
__device__ float         g_Dsq[B_ * LD_];         // 256 KB

// ---- kernel-2 smem layout (bytes) ----
#define SM_QS    0                      // 128x128 bf16 swizzled = 32768
#define SM_DS0   32768                  // bf16 chunk buf 0 (32768)
#define SM_DS1   65536                  // bf16 chunk buf 1 (32768)
#define SM_DSQ   98304                  // 512 floats (whole batch) = 2048
#define SM_QSQ   100352                 // 128 floats = 512
#define SM_MAX   100864                 // 128*4 floats = 2048
#define SM_RED   102912                 // 8 floats
#define SMEM_TOTAL (SM_RED + 64)

__device__ __forceinline__ uint32_t smem_u32(const void* p) {
    uint32_t a;
    asm("{ .reg .u64 t; cvta.to.shared.u64 t, %1; cvt.u32.u64 %0, t; }" : "=r"(a) : "l"(p));
    return a;
}

__device__ __forceinline__ void ldmatrix_x4(uint32_t& r0, uint32_t& r1,
                                            uint32_t& r2, uint32_t& r3, uint32_t addr) {
    asm volatile("ldmatrix.sync.aligned.m8n8.x4.shared.b16 {%0,%1,%2,%3}, [%4];"
                 : "=r"(r0), "=r"(r1), "=r"(r2), "=r"(r3) : "r"(addr));
}

__device__ __forceinline__ void mma_16816(float& c0, float& c1, float& c2, float& c3,
                                          uint32_t a0, uint32_t a1, uint32_t a2, uint32_t a3,
                                          uint32_t b0, uint32_t b1) {
    asm volatile("mma.sync.aligned.m16n8k16.row.col.f32.bf16.bf16.f32 "
                 "{%0,%1,%2,%3}, {%4,%5,%6,%7}, {%8,%9}, {%0,%1,%2,%3};"
                 : "+f"(c0), "+f"(c1), "+f"(c2), "+f"(c3)
                 : "r"(a0), "r"(a1), "r"(a2), "r"(a3), "r"(b0), "r"(b1));
}

__device__ __forceinline__ void cp_async16(uint32_t dst, const void* src) {
    asm volatile("cp.async.cg.shared.global [%0], [%1], 16;" :: "r"(dst), "l"(src));
}
__device__ __forceinline__ void cp_commit() {
    asm volatile("cp.async.commit_group;" ::: "memory");
}
template <int N>
__device__ __forceinline__ void cp_wait() {
    asm volatile("cp.async.wait_group %0;" :: "n"(N) : "memory");
}

// ================= kernel 1: D fp32 -> bf16 + exact row norms (+ zero out) ====
__global__ void __launch_bounds__(NTHREADS)
convert_d_kernel(const float* __restrict__ Dg, float* __restrict__ out) {
    const int tid = threadIdx.x;
    const int w = tid >> 5, l = tid & 31;
    const int rsub = l >> 3;
    const int piece = l & 7;

    if (blockIdx.x == 0 && tid < B_) out[tid] = 0.0f;

    #pragma unroll
    for (int pass = 0; pass < 4; pass++) {
        int row = blockIdx.x * 128 + w * 16 + pass * 4 + rsub;
        const float4* src = reinterpret_cast<const float4*>(Dg + (size_t)row * DIM);
        float4 v[4];
        #pragma unroll
        for (int i = 0; i < 4; i++) v[i] = src[piece + 8 * i];

        float s = 0.0f;
        #pragma unroll
        for (int i = 0; i < 4; i++)
            s += v[i].x * v[i].x + v[i].y * v[i].y + v[i].z * v[i].z + v[i].w * v[i].w;
        s += __shfl_xor_sync(0xffffffffu, s, 1);
        s += __shfl_xor_sync(0xffffffffu, s, 2);
        s += __shfl_xor_sync(0xffffffffu, s, 4);
        if (piece == 0) g_Dsq[row] = s;

        uint2* drow = reinterpret_cast<uint2*>(g_Dbf + (size_t)row * DIM);
        #pragma unroll
        for (int i = 0; i < 4; i++) {
            __nv_bfloat162 p0 = __floats2bfloat162_rn(v[i].x, v[i].y);
            __nv_bfloat162 p1 = __floats2bfloat162_rn(v[i].z, v[i].w);
            drow[piece + 8 * i] = make_uint2(*reinterpret_cast<uint32_t*>(&p0),
                                             *reinterpret_cast<uint32_t*>(&p1));
        }
    }
}

// ================= kernel 2: GEMM + fused max/sum epilogue =================
__global__ void __launch_bounds__(NTHREADS, 2)
colbert_mma_kernel(const float* __restrict__ Qg, float* __restrict__ out) {
    extern __shared__ char smem[];
    const uint32_t sb = smem_u32(smem);
    float* dsq_s  = reinterpret_cast<float*>(smem + SM_DSQ);
    float* qsq    = reinterpret_cast<float*>(smem + SM_QSQ);
    float* maxbuf = reinterpret_cast<float*>(smem + SM_MAX);
    float* red    = reinterpret_cast<float*>(smem + SM_RED);

    const int tid = threadIdx.x;
    const int w = tid >> 5, l = tid & 31;
    const int wm = w >> 2;               // 0..1
    const int wn = w & 3;                // 0..3

    const int b  = blockIdx.x >> 2;
    const int qt = blockIdx.x & 3;
    const float* Qb = Qg + ((size_t)(b * LQ_ + qt * TM)) * DIM;
    const __nv_bfloat16* Dbf_b = g_Dbf + (size_t)b * LD_ * DIM;

    // ---- issue cp.async for chunks 0 and 1 (bf16, swizzled dst) ----
    {
        #pragma unroll
        for (int cbuf = 0; cbuf < 2; cbuf++) {
            const char* src_base = reinterpret_cast<const char*>(Dbf_b + (size_t)cbuf * TN * DIM);
            uint32_t dst_base = sb + SM_DS0 + (uint32_t)(cbuf * 32768);
            #pragma unroll
            for (int j = 0; j < 8; j++) {
                int idx = tid + 256 * j;
                int r = idx >> 4, cc = idx & 15;
                cp_async16(dst_base + (uint32_t)(r * 256 + (((cc ^ (r & 7)) << 4))),
                           src_base + r * 256 + cc * 16);
            }
            cp_commit();
        }
    }

    // ---- convert Q tile fp32 -> bf16(2*q) swizzled smem + qsq (overlapped) ----
    {
        char* qs = smem + SM_QS;
        #pragma unroll
        for (int j = 0; j < TM / 8; j++) {
            int row = j * 8 + w;
            float4 v = reinterpret_cast<const float4*>(Qb)[row * 32 + l];
            float s = v.x * v.x + v.y * v.y + v.z * v.z + v.w * v.w;
            #pragma unroll
            for (int o = 16; o > 0; o >>= 1) s += __shfl_xor_sync(0xffffffffu, s, o);
            if (l == 0) qsq[row] = s;
            __nv_bfloat162 p0 = __floats2bfloat162_rn(2.0f * v.x, 2.0f * v.y);
            __nv_bfloat162 p1 = __floats2bfloat162_rn(2.0f * v.z, 2.0f * v.w);
            uint2 pk = make_uint2(*reinterpret_cast<uint32_t*>(&p0),
                                  *reinterpret_cast<uint32_t*>(&p1));
            uint32_t addr = (uint32_t)(row * 256 + (((l >> 1) ^ (row & 7)) << 4) + ((l & 1) << 3));
            *reinterpret_cast<uint2*>(qs + addr) = pk;
        }
    }
    // ---- whole-batch doc norms into smem (512 floats) ----
    {
        const float* src = g_Dsq + b * LD_;
        dsq_s[tid] = src[tid];
        dsq_s[tid + 256] = src[tid + 256];
    }

    // ---- ldmatrix lane addressing (validated round 3) ----
    const int jj = l >> 3;
    const int rr = l & 7;
    const int arow = wm * 64 + ((jj & 1) << 3) + rr;
    const int achunk_off = jj >> 1;
    const int asw = arow & 7;
    const int brow = wn * 32 + ((jj >> 1) << 3) + rr;
    const int bchunk_off = jj & 1;
    const int bsw = brow & 7;

    const int tg = l >> 2;
    const int tc = l & 3;

    float rlo[4], rhi[4];
    #pragma unroll
    for (int mt = 0; mt < 4; mt++) { rlo[mt] = -3.402823e38f; rhi[mt] = -3.402823e38f; }

    #pragma unroll
    for (int c = 0; c < NCHUNK; c++) {
        if (c < NCHUNK - 1) cp_wait<1>(); else cp_wait<0>();
        __syncthreads();   // chunk c visible to all

        const uint32_t ds_cur_u = sb + SM_DS0 + (uint32_t)((c & 1) * 32768);

        float acc[4][4][4];
        #pragma unroll
        for (int mt = 0; mt < 4; mt++)
            #pragma unroll
            for (int nt = 0; nt < 4; nt++)
                #pragma unroll
                for (int e = 0; e < 4; e++) acc[mt][nt][e] = 0.0f;

        // ---- double-buffered fragments: load k into buf (k&1), MMA from it next ----
        uint32_t a[2][4][4];
        uint32_t bf[2][4][2];

        // prologue: fragments for k=0 into buf 0
        #pragma unroll
        for (int mt = 0; mt < 4; mt++) {
            uint32_t addr = sb + SM_QS + (uint32_t)((arow + mt * 16) * 256
                          + ((achunk_off ^ asw) << 4));
            ldmatrix_x4(a[0][mt][0], a[0][mt][1], a[0][mt][2], a[0][mt][3], addr);
        }
        #pragma unroll
        for (int p = 0; p < 2; p++) {
            uint32_t addr = ds_cur_u + (uint32_t)((brow + p * 16) * 256
                          + ((bchunk_off ^ bsw) << 4));
            uint32_t r0, r1, r2, r3;
            ldmatrix_x4(r0, r1, r2, r3, addr);
            bf[0][p * 2 + 0][0] = r0; bf[0][p * 2 + 0][1] = r1;
            bf[0][p * 2 + 1][0] = r2; bf[0][p * 2 + 1][1] = r3;
        }

        #pragma unroll
        for (int k = 0; k < 8; k++) {
            const int cur = k & 1, nxt = cur ^ 1;
            // issue fragment loads for k+1 BEFORE the MMAs of k
            if (k < 7) {
                #pragma unroll
                for (int mt = 0; mt < 4; mt++) {
                    uint32_t addr = sb + SM_QS + (uint32_t)((arow + mt * 16) * 256
                                  + ((((k + 1) * 2 + achunk_off) ^ asw) << 4));
                    ldmatrix_x4(a[nxt][mt][0], a[nxt][mt][1], a[nxt][mt][2], a[nxt][mt][3], addr);
                }
                #pragma unroll
                for (int p = 0; p < 2; p++) {
                    uint32_t addr = ds_cur_u + (uint32_t)((brow + p * 16) * 256
                                  + ((((k + 1) * 2 + bchunk_off) ^ bsw) << 4));
                    uint32_t r0, r1, r2, r3;
                    ldmatrix_x4(r0, r1, r2, r3, addr);
                    bf[nxt][p * 2 + 0][0] = r0; bf[nxt][p * 2 + 0][1] = r1;
                    bf[nxt][p * 2 + 1][0] = r2; bf[nxt][p * 2 + 1][1] = r3;
                }
            }
            #pragma unroll
            for (int mt = 0; mt < 4; mt++)
                #pragma unroll
                for (int nt = 0; nt < 4; nt++)
                    mma_16816(acc[mt][nt][0], acc[mt][nt][1], acc[mt][nt][2], acc[mt][nt][3],
                              a[cur][mt][0], a[cur][mt][1], a[cur][mt][2], a[cur][mt][3],
                              bf[cur][nt][0], bf[cur][nt][1]);
        }

        // ---- refill this buffer with chunk c+2 ASAP (overlaps epilogue) ----
        if (c < NCHUNK - 2) {
            __syncthreads();   // all warps done with ldmatrix on this buffer
            const char* src_base = reinterpret_cast<const char*>(Dbf_b + (size_t)(c + 2) * TN * DIM);
            uint32_t dst_base = sb + SM_DS0 + (uint32_t)((c & 1) * 32768);
            #pragma unroll
            for (int j = 0; j < 8; j++) {
                int idx = tid + 256 * j;
                int r = idx >> 4, cc = idx & 15;
                cp_async16(dst_base + (uint32_t)(r * 256 + (((cc ^ (r & 7)) << 4))),
                           src_base + r * 256 + cc * 16);
            }
            cp_commit();
        }

        // ---- fused epilogue: neg_dist = (2q).d - d^2 ; running max ----
        #pragma unroll
        for (int nt = 0; nt < 4; nt++) {
            float2 ds2 = *reinterpret_cast<float2*>(&dsq_s[c * TN + wn * 32 + nt * 8 + tc * 2]);
            #pragma unroll
            for (int mt = 0; mt < 4; mt++) {
                rlo[mt] = fmaxf(rlo[mt], fmaxf(acc[mt][nt][0] - ds2.x, acc[mt][nt][1] - ds2.y));
                rhi[mt] = fmaxf(rhi[mt], fmaxf(acc[mt][nt][2] - ds2.x, acc[mt][nt][3] - ds2.y));
            }
        }
    }

    // ---- cross-lane max (cols in lane bits 0..1) ----
    #pragma unroll
    for (int mt = 0; mt < 4; mt++) {
        rlo[mt] = fmaxf(rlo[mt], __shfl_xor_sync(0xffffffffu, rlo[mt], 1));
        rlo[mt] = fmaxf(rlo[mt], __shfl_xor_sync(0xffffffffu, rlo[mt], 2));
        rhi[mt] = fmaxf(rhi[mt], __shfl_xor_sync(0xffffffffu, rhi[mt], 1));
        rhi[mt] = fmaxf(rhi[mt], __shfl_xor_sync(0xffffffffu, rhi[mt], 2));
    }
    if (tc == 0) {
        #pragma unroll
        for (int mt = 0; mt < 4; mt++) {
            maxbuf[(wm * 64 + mt * 16 + tg) * 4 + wn]     = rlo[mt];
            maxbuf[(wm * 64 + mt * 16 + 8 + tg) * 4 + wn] = rhi[mt];
        }
    }
    __syncthreads();

    // ---- row max across 4 warp-cols, subtract ||q||^2, block sum ----
    float val = 0.0f;
    if (tid < TM) {
        float4 m4 = *reinterpret_cast<float4*>(&maxbuf[tid * 4]);
        val = fmaxf(fmaxf(m4.x, m4.y), fmaxf(m4.z, m4.w)) - qsq[tid];
    }
    #pragma unroll
    for (int o = 16; o > 0; o >>= 1) val += __shfl_xor_sync(0xffffffffu, val, o);
    if (l == 0) red[w] = val;
    __syncthreads();
    if (tid == 0) {
        float s = 0.0f;
        #pragma unroll
        for (int i = 0; i < 8; i++) s += red[i];
        atomicAdd(&out[b], s);
    }
}

extern "C" void kernel_launch(void* const* d_in, const int* in_sizes, int n_in,
                              void* d_out, int out_size) {
    const float* Qg = (const float*)d_in[0];
    const float* Dg = (const float*)d_in[1];
    float* out = (float*)d_out;

    static int attr_set = 0;
    if (!attr_set) {
        cudaFuncSetAttribute(colbert_mma_kernel,
                             cudaFuncAttributeMaxDynamicSharedMemorySize, SMEM_TOTAL);
        attr_set = 1;
    }

    convert_d_kernel<<<(B_ * LD_) / 128, NTHREADS>>>(Dg, out);
    colbert_mma_kernel<<<B_ * (LQ_ / TM), NTHREADS, SMEM_TOTAL>>>(Qg, out);
}